// round 1
// baseline (speedup 1.0000x reference)
#include <cuda_runtime.h>

// Problem constants
static constexpr int Bc = 4, Tc = 2048, Cc = 1024, Hc = 16, Dc = 64;
static constexpr int Mrows = Bc * Tc;            // 8192
static constexpr int ELEMS = Mrows * Cc;         // 8388608

// Scratch (device globals — no allocation allowed)
__device__ float g_q[ELEMS];
__device__ float g_k[ELEMS];
__device__ float g_v[ELEMS];
__device__ float g_y[ELEMS];

// ---------------------------------------------------------------------------
// SGEMM NT with bias:  Cmat[m,n] = sum_k A[m,k] * Bw[n,k] + bias[n]
// A: [M,K] row-major, Bw: [N,K] row-major (nn.Linear weight), C: [M,N]
// 128x128x16 block tile, 8x8 per thread, 256 threads.
// ---------------------------------------------------------------------------
#define GBM 128
#define GBN 128
#define GBK 16

__global__ __launch_bounds__(256)
void sgemm_nt_bias(const float* __restrict__ A,
                   const float* __restrict__ Bw,
                   const float* __restrict__ bias,
                   float* __restrict__ Cmat,
                   int M, int N, int K)
{
    __shared__ float As[GBK][GBM];
    __shared__ float Bs[GBK][GBN];

    const int tid = threadIdx.x;
    const int tx = tid & 15;        // 0..15 -> N
    const int ty = tid >> 4;        // 0..15 -> M

    const float* Ab = A  + (size_t)blockIdx.y * GBM * K;
    const float* Bb = Bw + (size_t)blockIdx.x * GBN * K;

    float acc[8][8];
#pragma unroll
    for (int i = 0; i < 8; i++)
#pragma unroll
        for (int j = 0; j < 8; j++) acc[i][j] = 0.f;

    for (int k0 = 0; k0 < K; k0 += GBK) {
#pragma unroll
        for (int u = 0; u < 2; u++) {
            int id = tid + u * 256;        // 0..511
            int r  = id >> 2;              // 0..127
            int c  = (id & 3) << 2;        // 0,4,8,12
            float4 va = *(const float4*)(Ab + (size_t)r * K + k0 + c);
            As[c + 0][r] = va.x; As[c + 1][r] = va.y;
            As[c + 2][r] = va.z; As[c + 3][r] = va.w;
            float4 vb = *(const float4*)(Bb + (size_t)r * K + k0 + c);
            Bs[c + 0][r] = vb.x; Bs[c + 1][r] = vb.y;
            Bs[c + 2][r] = vb.z; Bs[c + 3][r] = vb.w;
        }
        __syncthreads();

#pragma unroll
        for (int k = 0; k < GBK; k++) {
            const float4* a4 = (const float4*)&As[k][ty * 8];
            const float4* b4 = (const float4*)&Bs[k][tx * 8];
            float4 ra0 = a4[0], ra1 = a4[1];
            float4 rb0 = b4[0], rb1 = b4[1];
            float ra[8] = {ra0.x, ra0.y, ra0.z, ra0.w, ra1.x, ra1.y, ra1.z, ra1.w};
            float rb[8] = {rb0.x, rb0.y, rb0.z, rb0.w, rb1.x, rb1.y, rb1.z, rb1.w};
#pragma unroll
            for (int i = 0; i < 8; i++)
#pragma unroll
                for (int j = 0; j < 8; j++)
                    acc[i][j] = fmaf(ra[i], rb[j], acc[i][j]);
        }
        __syncthreads();
    }

    const int row0 = blockIdx.y * GBM + ty * 8;
    const int col0 = blockIdx.x * GBN + tx * 8;
    float bb[8];
#pragma unroll
    for (int j = 0; j < 8; j++) bb[j] = bias[col0 + j];
#pragma unroll
    for (int i = 0; i < 8; i++) {
        float4 o0 = make_float4(acc[i][0] + bb[0], acc[i][1] + bb[1],
                                acc[i][2] + bb[2], acc[i][3] + bb[3]);
        float4 o1 = make_float4(acc[i][4] + bb[4], acc[i][5] + bb[5],
                                acc[i][6] + bb[6], acc[i][7] + bb[7]);
        *(float4*)&Cmat[(size_t)(row0 + i) * N + col0]     = o0;
        *(float4*)&Cmat[(size_t)(row0 + i) * N + col0 + 4] = o1;
    }
}

// ---------------------------------------------------------------------------
// Flash-style causal attention, fp32.
// q/k/v laid out [B,T,C] with head h at columns h*64..h*64+63.
// Grid: (T/64, H, B). Block: 256 threads, 64x64 S tile, 4x4 per thread.
// ---------------------------------------------------------------------------
static constexpr int KT_STRIDE = 68;   // padded stride (multiple of 4 for LDS.128)
// smem layout (floats): Qs[64*64] | Kt[64*68] | Ps[64*68] | Vs[64*64]
static constexpr int SM_QS = 0;
static constexpr int SM_KT = SM_QS + 64 * 64;
static constexpr int SM_PS = SM_KT + 64 * KT_STRIDE;
static constexpr int SM_VS = SM_PS + 64 * KT_STRIDE;
static constexpr int ATT_SMEM_FLOATS = SM_VS + 64 * 64;
static constexpr int ATT_SMEM_BYTES = ATT_SMEM_FLOATS * 4;   // 67584

__global__ __launch_bounds__(256)
void attn_kernel(const float* __restrict__ Q,
                 const float* __restrict__ K,
                 const float* __restrict__ V,
                 float* __restrict__ Y)
{
    const int qi = blockIdx.x;   // q tile
    const int h  = blockIdx.y;
    const int b  = blockIdx.z;
    const int tid = threadIdx.x;
    const int tx = tid & 15;     // key / d columns
    const int ty = tid >> 4;     // q rows

    extern __shared__ float sm[];
    float* Qs = sm + SM_QS;   // [r][d] stride 64
    float* Kt = sm + SM_KT;   // [d][s] stride 68
    float* Ps = sm + SM_PS;   // [r][s] stride 68
    float* Vs = sm + SM_VS;   // [s][d] stride 64

    const size_t base = (size_t)b * Tc * Cc + (size_t)h * Dc;
    const float scale = 0.125f;  // 1/sqrt(64)

    // Load Q tile (scaled) -> Qs[r][d]
#pragma unroll
    for (int u = 0; u < 4; u++) {
        int id = tid + u * 256;          // 0..1023
        int r  = id >> 4;                // 0..63
        int c  = (id & 15) << 2;         // 0..60
        float4 v = *(const float4*)(Q + base + (size_t)(qi * 64 + r) * Cc + c);
        float* dst = Qs + r * 64 + c;
        dst[0] = v.x * scale; dst[1] = v.y * scale;
        dst[2] = v.z * scale; dst[3] = v.w * scale;
    }

    float m_i[4], l_i[4], O[4][4];
#pragma unroll
    for (int i = 0; i < 4; i++) {
        m_i[i] = -1e30f; l_i[i] = 0.f;
#pragma unroll
        for (int j = 0; j < 4; j++) O[i][j] = 0.f;
    }

    for (int st = 0; st <= qi; st++) {
        __syncthreads();  // previous iteration done with Kt/Ps/Vs (and no-op at st=0)

        // Load K tile transposed -> Kt[d][s]; V tile natural -> Vs[s][d]
#pragma unroll
        for (int u = 0; u < 4; u++) {
            int id = tid + u * 256;
            int s  = id >> 4;
            int c  = (id & 15) << 2;
            float4 kv = *(const float4*)(K + base + (size_t)(st * 64 + s) * Cc + c);
            Kt[(c + 0) * KT_STRIDE + s] = kv.x;
            Kt[(c + 1) * KT_STRIDE + s] = kv.y;
            Kt[(c + 2) * KT_STRIDE + s] = kv.z;
            Kt[(c + 3) * KT_STRIDE + s] = kv.w;
            float4 vv = *(const float4*)(V + base + (size_t)(st * 64 + s) * Cc + c);
            float* vd = Vs + s * 64 + c;
            vd[0] = vv.x; vd[1] = vv.y; vd[2] = vv.z; vd[3] = vv.w;
        }
        __syncthreads();

        // S = (Q*scale) K^T   (4x4 per thread, d-chunked by 4 for LDS.128)
        float S[4][4];
#pragma unroll
        for (int i = 0; i < 4; i++)
#pragma unroll
            for (int j = 0; j < 4; j++) S[i][j] = 0.f;

#pragma unroll
        for (int d0 = 0; d0 < 64; d0 += 4) {
            float4 qa[4], kb[4];
#pragma unroll
            for (int i = 0; i < 4; i++)
                qa[i] = *(const float4*)&Qs[(ty * 4 + i) * 64 + d0];
#pragma unroll
            for (int dd = 0; dd < 4; dd++)
                kb[dd] = *(const float4*)&Kt[(d0 + dd) * KT_STRIDE + tx * 4];
#pragma unroll
            for (int i = 0; i < 4; i++) {
                const float qa4[4] = {qa[i].x, qa[i].y, qa[i].z, qa[i].w};
#pragma unroll
                for (int dd = 0; dd < 4; dd++) {
                    const float kbv[4] = {kb[dd].x, kb[dd].y, kb[dd].z, kb[dd].w};
#pragma unroll
                    for (int j = 0; j < 4; j++)
                        S[i][j] = fmaf(qa4[dd], kbv[j], S[i][j]);
                }
            }
        }

        // Causal mask on the diagonal tile
        if (st == qi) {
#pragma unroll
            for (int i = 0; i < 4; i++)
#pragma unroll
                for (int j = 0; j < 4; j++)
                    if (tx * 4 + j > ty * 4 + i) S[i][j] = -1e30f;
        }

        // Online softmax update (row groups of 16 lanes: offsets 1,2,4,8)
#pragma unroll
        for (int i = 0; i < 4; i++) {
            float rmax = fmaxf(fmaxf(S[i][0], S[i][1]), fmaxf(S[i][2], S[i][3]));
#pragma unroll
            for (int off = 1; off < 16; off <<= 1)
                rmax = fmaxf(rmax, __shfl_xor_sync(0xffffffffu, rmax, off));
            float m_new = fmaxf(m_i[i], rmax);
            float alpha = __expf(m_i[i] - m_new);
            float rsum = 0.f;
#pragma unroll
            for (int j = 0; j < 4; j++) {
                S[i][j] = __expf(S[i][j] - m_new);
                rsum += S[i][j];
            }
#pragma unroll
            for (int off = 1; off < 16; off <<= 1)
                rsum += __shfl_xor_sync(0xffffffffu, rsum, off);
            l_i[i] = l_i[i] * alpha + rsum;
            m_i[i] = m_new;
#pragma unroll
            for (int j = 0; j < 4; j++) O[i][j] *= alpha;
        }

        // Stage P to smem
#pragma unroll
        for (int i = 0; i < 4; i++) {
            float4 pv = make_float4(S[i][0], S[i][1], S[i][2], S[i][3]);
            *(float4*)&Ps[(ty * 4 + i) * KT_STRIDE + tx * 4] = pv;
        }
        __syncthreads();

        // O += P @ V   (s-chunked by 4)
#pragma unroll
        for (int s0 = 0; s0 < 64; s0 += 4) {
            float4 pa[4], vb[4];
#pragma unroll
            for (int i = 0; i < 4; i++)
                pa[i] = *(const float4*)&Ps[(ty * 4 + i) * KT_STRIDE + s0];
#pragma unroll
            for (int ss = 0; ss < 4; ss++)
                vb[ss] = *(const float4*)&Vs[(s0 + ss) * 64 + tx * 4];
#pragma unroll
            for (int i = 0; i < 4; i++) {
                const float pav[4] = {pa[i].x, pa[i].y, pa[i].z, pa[i].w};
#pragma unroll
                for (int ss = 0; ss < 4; ss++) {
                    const float vbv[4] = {vb[ss].x, vb[ss].y, vb[ss].z, vb[ss].w};
#pragma unroll
                    for (int j = 0; j < 4; j++)
                        O[i][j] = fmaf(pav[ss], vbv[j], O[i][j]);
                }
            }
        }
    }

    // Epilogue: Y[b, t, h*64 + d] = O / l
#pragma unroll
    for (int i = 0; i < 4; i++) {
        float inv = 1.f / l_i[i];
        float4 o = make_float4(O[i][0] * inv, O[i][1] * inv,
                               O[i][2] * inv, O[i][3] * inv);
        size_t t = (size_t)(qi * 64 + ty * 4 + i);
        *(float4*)&Y[((size_t)b * Tc + t) * Cc + h * Dc + tx * 4] = o;
    }
}

// ---------------------------------------------------------------------------
extern "C" void kernel_launch(void* const* d_in, const int* in_sizes, int n_in,
                              void* d_out, int out_size)
{
    (void)in_sizes; (void)n_in; (void)out_size;
    const float* x  = (const float*)d_in[0];
    const float* Wq = (const float*)d_in[1];
    const float* bq = (const float*)d_in[2];
    const float* Wk = (const float*)d_in[3];
    const float* bk = (const float*)d_in[4];
    const float* Wv = (const float*)d_in[5];
    const float* bv = (const float*)d_in[6];
    const float* Wp = (const float*)d_in[7];
    const float* bp = (const float*)d_in[8];
    float* out = (float*)d_out;

    float *q, *k, *v, *y;
    cudaGetSymbolAddress((void**)&q, g_q);
    cudaGetSymbolAddress((void**)&k, g_k);
    cudaGetSymbolAddress((void**)&v, g_v);
    cudaGetSymbolAddress((void**)&y, g_y);

    cudaFuncSetAttribute(attn_kernel,
                         cudaFuncAttributeMaxDynamicSharedMemorySize,
                         ATT_SMEM_BYTES);

    dim3 gg(Cc / GBN, Mrows / GBM);   // (8, 64)
    sgemm_nt_bias<<<gg, 256>>>(x, Wq, bq, q, Mrows, Cc, Cc);
    sgemm_nt_bias<<<gg, 256>>>(x, Wk, bk, k, Mrows, Cc, Cc);
    sgemm_nt_bias<<<gg, 256>>>(x, Wv, bv, v, Mrows, Cc, Cc);

    dim3 ga(Tc / 64, Hc, Bc);         // (32, 16, 4)
    attn_kernel<<<ga, 256, ATT_SMEM_BYTES>>>(q, k, v, y);

    sgemm_nt_bias<<<gg, 256>>>(y, Wp, bp, out, Mrows, Cc, Cc);
}

// round 3
// speedup vs baseline: 1.1805x; 1.1805x over previous
#include <cuda_runtime.h>
#include <cuda_bf16.h>
#include <mma.h>
#include <cstdint>

using namespace nvcuda;

// Problem constants
static constexpr int Bc = 4, Tc = 2048, Cc = 1024, Hc = 16, Dc = 64;
static constexpr int Mrows = Bc * Tc;            // 8192
static constexpr int ELEMS = Mrows * Cc;         // 8388608
static constexpr int WELEMS = Cc * Cc;           // 1048576

// Scratch (device globals — no allocation allowed)
__device__ float g_q[ELEMS];
__device__ float g_k[ELEMS];
__device__ float g_v[ELEMS];
__device__ float g_y[ELEMS];
__device__ __nv_bfloat16 g_xhi[ELEMS], g_xlo[ELEMS];
__device__ __nv_bfloat16 g_yhi[ELEMS], g_ylo[ELEMS];
__device__ __nv_bfloat16 g_whi[4][WELEMS], g_wlo[4][WELEMS];

// ---------------------------------------------------------------------------
// fp32 -> bf16 hi/lo split conversion
// ---------------------------------------------------------------------------
__global__ __launch_bounds__(256)
void split_bf16(const float* __restrict__ in,
                __nv_bfloat16* __restrict__ hi,
                __nv_bfloat16* __restrict__ lo, int n4)
{
    int i = blockIdx.x * blockDim.x + threadIdx.x;
    if (i >= n4) return;
    int idx = i * 4;
    float4 v = *(const float4*)(in + idx);
    __nv_bfloat16 h0 = __float2bfloat16_rn(v.x);
    __nv_bfloat16 h1 = __float2bfloat16_rn(v.y);
    __nv_bfloat16 h2 = __float2bfloat16_rn(v.z);
    __nv_bfloat16 h3 = __float2bfloat16_rn(v.w);
    __nv_bfloat16 l0 = __float2bfloat16_rn(v.x - __bfloat162float(h0));
    __nv_bfloat16 l1 = __float2bfloat16_rn(v.y - __bfloat162float(h1));
    __nv_bfloat16 l2 = __float2bfloat16_rn(v.z - __bfloat162float(h2));
    __nv_bfloat16 l3 = __float2bfloat16_rn(v.w - __bfloat162float(h3));
    ushort4 hs, ls;
    hs.x = __bfloat16_as_ushort(h0); hs.y = __bfloat16_as_ushort(h1);
    hs.z = __bfloat16_as_ushort(h2); hs.w = __bfloat16_as_ushort(h3);
    ls.x = __bfloat16_as_ushort(l0); ls.y = __bfloat16_as_ushort(l1);
    ls.z = __bfloat16_as_ushort(l2); ls.w = __bfloat16_as_ushort(l3);
    *(ushort4*)(hi + idx) = hs;
    *(ushort4*)(lo + idx) = ls;
}

// ---------------------------------------------------------------------------
// HMMA (wmma) split-precision GEMM-NT with bias.
// C[m,n] = sum_k A[m,k]*B[n,k] + bias[n], computed as
//   Ahi*Bhi + Alo*Bhi + Ahi*Blo, fp32 accumulate.
// Block tile 128x128, K-chunk 16, 8 warps (4 M x 2 N), warp tile 32x64.
// ---------------------------------------------------------------------------
#define WBM 128
#define WBN 128
#define WBK 16
#define ASTR 24          // WBK + 8 pad (multiple of 8 elems for wmma ldm)
#define BSTRIDE 132      // bias tile row stride (floats)

__global__ __launch_bounds__(256, 1)
void gemm_wmma_split(const __nv_bfloat16* __restrict__ Ahi,
                     const __nv_bfloat16* __restrict__ Alo,
                     const __nv_bfloat16* __restrict__ Bhi,
                     const __nv_bfloat16* __restrict__ Blo,
                     const float* __restrict__ bias,
                     float* __restrict__ Cmat,
                     int M, int N, int K)
{
    __shared__ __nv_bfloat16 sAh[WBM * ASTR];
    __shared__ __nv_bfloat16 sAl[WBM * ASTR];
    __shared__ __nv_bfloat16 sBh[WBN * ASTR];
    __shared__ __nv_bfloat16 sBl[WBN * ASTR];
    __shared__ float biasT[16 * BSTRIDE];

    const int tid = threadIdx.x;
    const int wid = tid >> 5;
    const int wm = wid & 3;          // 0..3  -> M
    const int wn = wid >> 2;         // 0..1  -> N
    const int m0 = blockIdx.y * WBM;
    const int n0 = blockIdx.x * WBN;

    // bias tile: 16 identical rows of bias[n0..n0+127]
    for (int i = tid; i < 16 * 128; i += 256) {
        int r = i >> 7, c = i & 127;
        biasT[r * BSTRIDE + c] = bias[n0 + c];
    }
    __syncthreads();

    wmma::fragment<wmma::accumulator, 16, 16, 16, float> acc[2][4];
#pragma unroll
    for (int i = 0; i < 2; i++)
#pragma unroll
        for (int j = 0; j < 4; j++)
            wmma::load_matrix_sync(acc[i][j], &biasT[wn * 64 + j * 16],
                                   BSTRIDE, wmma::mem_row_major);

    const int lr = tid >> 1;               // 0..127 row
    const int lc = (tid & 1) * 8;          // 0 or 8

    const __nv_bfloat16* pAh = Ahi + (size_t)(m0 + lr) * K + lc;
    const __nv_bfloat16* pAl = Alo + (size_t)(m0 + lr) * K + lc;
    const __nv_bfloat16* pBh = Bhi + (size_t)(n0 + lr) * K + lc;
    const __nv_bfloat16* pBl = Blo + (size_t)(n0 + lr) * K + lc;
    __nv_bfloat16* dA_h = &sAh[lr * ASTR + lc];
    __nv_bfloat16* dA_l = &sAl[lr * ASTR + lc];
    __nv_bfloat16* dB_h = &sBh[lr * ASTR + lc];
    __nv_bfloat16* dB_l = &sBl[lr * ASTR + lc];

    for (int k0 = 0; k0 < K; k0 += WBK) {
        *(uint4*)dA_h = *(const uint4*)(pAh + k0);
        *(uint4*)dA_l = *(const uint4*)(pAl + k0);
        *(uint4*)dB_h = *(const uint4*)(pBh + k0);
        *(uint4*)dB_l = *(const uint4*)(pBl + k0);
        __syncthreads();

        wmma::fragment<wmma::matrix_a, 16, 16, 16, __nv_bfloat16, wmma::row_major> ah[2], al[2];
        wmma::fragment<wmma::matrix_b, 16, 16, 16, __nv_bfloat16, wmma::col_major> bh[4], bl[4];
#pragma unroll
        for (int i = 0; i < 2; i++) {
            wmma::load_matrix_sync(ah[i], &sAh[(wm * 32 + i * 16) * ASTR], ASTR);
            wmma::load_matrix_sync(al[i], &sAl[(wm * 32 + i * 16) * ASTR], ASTR);
        }
#pragma unroll
        for (int j = 0; j < 4; j++) {
            wmma::load_matrix_sync(bh[j], &sBh[(wn * 64 + j * 16) * ASTR], ASTR);
            wmma::load_matrix_sync(bl[j], &sBl[(wn * 64 + j * 16) * ASTR], ASTR);
        }
#pragma unroll
        for (int i = 0; i < 2; i++)
#pragma unroll
            for (int j = 0; j < 4; j++) {
                wmma::mma_sync(acc[i][j], ah[i], bh[j], acc[i][j]);
                wmma::mma_sync(acc[i][j], al[i], bh[j], acc[i][j]);
                wmma::mma_sync(acc[i][j], ah[i], bl[j], acc[i][j]);
            }
        __syncthreads();
    }

#pragma unroll
    for (int i = 0; i < 2; i++)
#pragma unroll
        for (int j = 0; j < 4; j++)
            wmma::store_matrix_sync(
                &Cmat[(size_t)(m0 + wm * 32 + i * 16) * N + n0 + wn * 64 + j * 16],
                acc[i][j], N, wmma::mem_row_major);
}

// ---------------------------------------------------------------------------
// Flash-style causal attention, fp32 (R1, passing).
// ---------------------------------------------------------------------------
static constexpr int KT_STRIDE = 68;
static constexpr int SM_QS = 0;
static constexpr int SM_KT = SM_QS + 64 * 64;
static constexpr int SM_PS = SM_KT + 64 * KT_STRIDE;
static constexpr int SM_VS = SM_PS + 64 * KT_STRIDE;
static constexpr int ATT_SMEM_FLOATS = SM_VS + 64 * 64;
static constexpr int ATT_SMEM_BYTES = ATT_SMEM_FLOATS * 4;

__global__ __launch_bounds__(256)
void attn_kernel(const float* __restrict__ Q,
                 const float* __restrict__ K,
                 const float* __restrict__ V,
                 float* __restrict__ Y)
{
    const int qi = blockIdx.x;
    const int h  = blockIdx.y;
    const int b  = blockIdx.z;
    const int tid = threadIdx.x;
    const int tx = tid & 15;
    const int ty = tid >> 4;

    extern __shared__ float sm[];
    float* Qs = sm + SM_QS;
    float* Kt = sm + SM_KT;
    float* Ps = sm + SM_PS;
    float* Vs = sm + SM_VS;

    const size_t base = (size_t)b * Tc * Cc + (size_t)h * Dc;
    const float scale = 0.125f;

#pragma unroll
    for (int u = 0; u < 4; u++) {
        int id = tid + u * 256;
        int r  = id >> 4;
        int c  = (id & 15) << 2;
        float4 v = *(const float4*)(Q + base + (size_t)(qi * 64 + r) * Cc + c);
        float* dst = Qs + r * 64 + c;
        dst[0] = v.x * scale; dst[1] = v.y * scale;
        dst[2] = v.z * scale; dst[3] = v.w * scale;
    }

    float m_i[4], l_i[4], O[4][4];
#pragma unroll
    for (int i = 0; i < 4; i++) {
        m_i[i] = -1e30f; l_i[i] = 0.f;
#pragma unroll
        for (int j = 0; j < 4; j++) O[i][j] = 0.f;
    }

    for (int st = 0; st <= qi; st++) {
        __syncthreads();
#pragma unroll
        for (int u = 0; u < 4; u++) {
            int id = tid + u * 256;
            int s  = id >> 4;
            int c  = (id & 15) << 2;
            float4 kv = *(const float4*)(K + base + (size_t)(st * 64 + s) * Cc + c);
            Kt[(c + 0) * KT_STRIDE + s] = kv.x;
            Kt[(c + 1) * KT_STRIDE + s] = kv.y;
            Kt[(c + 2) * KT_STRIDE + s] = kv.z;
            Kt[(c + 3) * KT_STRIDE + s] = kv.w;
            float4 vv = *(const float4*)(V + base + (size_t)(st * 64 + s) * Cc + c);
            float* vd = Vs + s * 64 + c;
            vd[0] = vv.x; vd[1] = vv.y; vd[2] = vv.z; vd[3] = vv.w;
        }
        __syncthreads();

        float S[4][4];
#pragma unroll
        for (int i = 0; i < 4; i++)
#pragma unroll
            for (int j = 0; j < 4; j++) S[i][j] = 0.f;

#pragma unroll
        for (int d0 = 0; d0 < 64; d0 += 4) {
            float4 qa[4], kb[4];
#pragma unroll
            for (int i = 0; i < 4; i++)
                qa[i] = *(const float4*)&Qs[(ty * 4 + i) * 64 + d0];
#pragma unroll
            for (int dd = 0; dd < 4; dd++)
                kb[dd] = *(const float4*)&Kt[(d0 + dd) * KT_STRIDE + tx * 4];
#pragma unroll
            for (int i = 0; i < 4; i++) {
                const float qa4[4] = {qa[i].x, qa[i].y, qa[i].z, qa[i].w};
#pragma unroll
                for (int dd = 0; dd < 4; dd++) {
                    const float kbv[4] = {kb[dd].x, kb[dd].y, kb[dd].z, kb[dd].w};
#pragma unroll
                    for (int j = 0; j < 4; j++)
                        S[i][j] = fmaf(qa4[dd], kbv[j], S[i][j]);
                }
            }
        }

        if (st == qi) {
#pragma unroll
            for (int i = 0; i < 4; i++)
#pragma unroll
                for (int j = 0; j < 4; j++)
                    if (tx * 4 + j > ty * 4 + i) S[i][j] = -1e30f;
        }

#pragma unroll
        for (int i = 0; i < 4; i++) {
            float rmax = fmaxf(fmaxf(S[i][0], S[i][1]), fmaxf(S[i][2], S[i][3]));
#pragma unroll
            for (int off = 1; off < 16; off <<= 1)
                rmax = fmaxf(rmax, __shfl_xor_sync(0xffffffffu, rmax, off));
            float m_new = fmaxf(m_i[i], rmax);
            float alpha = __expf(m_i[i] - m_new);
            float rsum = 0.f;
#pragma unroll
            for (int j = 0; j < 4; j++) {
                S[i][j] = __expf(S[i][j] - m_new);
                rsum += S[i][j];
            }
#pragma unroll
            for (int off = 1; off < 16; off <<= 1)
                rsum += __shfl_xor_sync(0xffffffffu, rsum, off);
            l_i[i] = l_i[i] * alpha + rsum;
            m_i[i] = m_new;
#pragma unroll
            for (int j = 0; j < 4; j++) O[i][j] *= alpha;
        }

#pragma unroll
        for (int i = 0; i < 4; i++) {
            float4 pv = make_float4(S[i][0], S[i][1], S[i][2], S[i][3]);
            *(float4*)&Ps[(ty * 4 + i) * KT_STRIDE + tx * 4] = pv;
        }
        __syncthreads();

#pragma unroll
        for (int s0 = 0; s0 < 64; s0 += 4) {
            float4 pa[4], vb[4];
#pragma unroll
            for (int i = 0; i < 4; i++)
                pa[i] = *(const float4*)&Ps[(ty * 4 + i) * KT_STRIDE + s0];
#pragma unroll
            for (int ss = 0; ss < 4; ss++)
                vb[ss] = *(const float4*)&Vs[(s0 + ss) * 64 + tx * 4];
#pragma unroll
            for (int i = 0; i < 4; i++) {
                const float pav[4] = {pa[i].x, pa[i].y, pa[i].z, pa[i].w};
#pragma unroll
                for (int ss = 0; ss < 4; ss++) {
                    const float vbv[4] = {vb[ss].x, vb[ss].y, vb[ss].z, vb[ss].w};
#pragma unroll
                    for (int j = 0; j < 4; j++)
                        O[i][j] = fmaf(pav[ss], vbv[j], O[i][j]);
                }
            }
        }
    }

#pragma unroll
    for (int i = 0; i < 4; i++) {
        float inv = 1.f / l_i[i];
        float4 o = make_float4(O[i][0] * inv, O[i][1] * inv,
                               O[i][2] * inv, O[i][3] * inv);
        size_t t = (size_t)(qi * 64 + ty * 4 + i);
        *(float4*)&Y[((size_t)b * Tc + t) * Cc + h * Dc + tx * 4] = o;
    }
}

// ---------------------------------------------------------------------------
extern "C" void kernel_launch(void* const* d_in, const int* in_sizes, int n_in,
                              void* d_out, int out_size)
{
    (void)in_sizes; (void)n_in; (void)out_size;
    const float* x  = (const float*)d_in[0];
    const float* Wq = (const float*)d_in[1];
    const float* bq = (const float*)d_in[2];
    const float* Wk = (const float*)d_in[3];
    const float* bk = (const float*)d_in[4];
    const float* Wv = (const float*)d_in[5];
    const float* bv = (const float*)d_in[6];
    const float* Wp = (const float*)d_in[7];
    const float* bp = (const float*)d_in[8];
    float* out = (float*)d_out;

    float *q, *k, *v, *y;
    __nv_bfloat16 *xhi, *xlo, *yhi, *ylo, *whi, *wlo;
    cudaGetSymbolAddress((void**)&q, g_q);
    cudaGetSymbolAddress((void**)&k, g_k);
    cudaGetSymbolAddress((void**)&v, g_v);
    cudaGetSymbolAddress((void**)&y, g_y);
    cudaGetSymbolAddress((void**)&xhi, g_xhi);
    cudaGetSymbolAddress((void**)&xlo, g_xlo);
    cudaGetSymbolAddress((void**)&yhi, g_yhi);
    cudaGetSymbolAddress((void**)&ylo, g_ylo);
    cudaGetSymbolAddress((void**)&whi, g_whi);
    cudaGetSymbolAddress((void**)&wlo, g_wlo);

    cudaFuncSetAttribute(attn_kernel,
                         cudaFuncAttributeMaxDynamicSharedMemorySize, ATT_SMEM_BYTES);

    // hi/lo splits
    split_bf16<<<(ELEMS / 4 + 255) / 256, 256>>>(x, xhi, xlo, ELEMS / 4);
    const float* Ws[4] = {Wq, Wk, Wv, Wp};
    for (int i = 0; i < 4; i++)
        split_bf16<<<(WELEMS / 4 + 255) / 256, 256>>>(
            Ws[i], whi + (size_t)i * WELEMS, wlo + (size_t)i * WELEMS, WELEMS / 4);

    // QKV projections (HMMA split precision)
    dim3 gg(Cc / WBN, Mrows / WBM);   // (8, 64)
    gemm_wmma_split<<<gg, 256>>>(xhi, xlo, whi + 0 * (size_t)WELEMS,
                                 wlo + 0 * (size_t)WELEMS, bq, q, Mrows, Cc, Cc);
    gemm_wmma_split<<<gg, 256>>>(xhi, xlo, whi + 1 * (size_t)WELEMS,
                                 wlo + 1 * (size_t)WELEMS, bk, k, Mrows, Cc, Cc);
    gemm_wmma_split<<<gg, 256>>>(xhi, xlo, whi + 2 * (size_t)WELEMS,
                                 wlo + 2 * (size_t)WELEMS, bv, v, Mrows, Cc, Cc);

    // attention (fp32)
    dim3 ga(Tc / 64, Hc, Bc);
    attn_kernel<<<ga, 256, ATT_SMEM_BYTES>>>(q, k, v, y);

    // output projection
    split_bf16<<<(ELEMS / 4 + 255) / 256, 256>>>(y, yhi, ylo, ELEMS / 4);
    gemm_wmma_split<<<gg, 256>>>(yhi, ylo, whi + 3 * (size_t)WELEMS,
                                 wlo + 3 * (size_t)WELEMS, bp, out, Mrows, Cc, Cc);
}

// round 4
// speedup vs baseline: 2.3190x; 1.9644x over previous
#include <cuda_runtime.h>
#include <cuda_bf16.h>
#include <mma.h>
#include <cstdint>

using namespace nvcuda;

// Problem constants
static constexpr int Bc = 4, Tc = 2048, Cc = 1024, Hc = 16, Dc = 64;
static constexpr int Mrows = Bc * Tc;            // 8192
static constexpr int ELEMS = Mrows * Cc;         // 8388608
static constexpr int WELEMS = Cc * Cc;           // 1048576

// Scratch (device globals — no allocation allowed)
__device__ float g_q[ELEMS];
__device__ float g_k[ELEMS];
__device__ float g_v[ELEMS];
__device__ float g_y[ELEMS];
__device__ __nv_bfloat16 g_xhi[ELEMS], g_xlo[ELEMS];
__device__ __nv_bfloat16 g_yhi[ELEMS], g_ylo[ELEMS];
__device__ __nv_bfloat16 g_whi[4][WELEMS], g_wlo[4][WELEMS];

// ---------------------------------------------------------------------------
// PTX primitives (all plain-sm_103 legal: ldmatrix sm_75+, mma.sync sm_80+)
// ---------------------------------------------------------------------------
__device__ __forceinline__ uint32_t smem_u32(const void* p) {
    uint32_t a;
    asm("{ .reg .u64 t; cvta.to.shared.u64 t, %1; cvt.u32.u64 %0, t; }" : "=r"(a) : "l"(p));
    return a;
}
__device__ __forceinline__ void ldsm4(uint32_t& r0, uint32_t& r1, uint32_t& r2, uint32_t& r3, uint32_t a) {
    asm volatile("ldmatrix.sync.aligned.m8n8.x4.shared.b16 {%0,%1,%2,%3}, [%4];"
                 : "=r"(r0), "=r"(r1), "=r"(r2), "=r"(r3) : "r"(a));
}
__device__ __forceinline__ void ldsm2(uint32_t& r0, uint32_t& r1, uint32_t a) {
    asm volatile("ldmatrix.sync.aligned.m8n8.x2.shared.b16 {%0,%1}, [%2];"
                 : "=r"(r0), "=r"(r1) : "r"(a));
}
__device__ __forceinline__ void ldsm2t(uint32_t& r0, uint32_t& r1, uint32_t a) {
    asm volatile("ldmatrix.sync.aligned.m8n8.x2.trans.shared.b16 {%0,%1}, [%2];"
                 : "=r"(r0), "=r"(r1) : "r"(a));
}
__device__ __forceinline__ void mma16816(float* c, uint32_t a0, uint32_t a1, uint32_t a2, uint32_t a3,
                                         uint32_t b0, uint32_t b1) {
    asm volatile("mma.sync.aligned.m16n8k16.row.col.f32.bf16.bf16.f32 "
                 "{%0,%1,%2,%3}, {%4,%5,%6,%7}, {%8,%9}, {%0,%1,%2,%3};"
                 : "+f"(c[0]), "+f"(c[1]), "+f"(c[2]), "+f"(c[3])
                 : "r"(a0), "r"(a1), "r"(a2), "r"(a3), "r"(b0), "r"(b1));
}
// split x into bf16 hi/lo pair; pack (even,odd) columns into one b32 each
__device__ __forceinline__ void split_pack(float x, float y, uint32_t& hi, uint32_t& lo) {
    __nv_bfloat16 hx = __float2bfloat16_rn(x), hy = __float2bfloat16_rn(y);
    float lx = x - __bfloat162float(hx), ly = y - __bfloat162float(hy);
    __nv_bfloat162 hv(hx, hy);
    __nv_bfloat162 lv(__float2bfloat16_rn(lx), __float2bfloat16_rn(ly));
    hi = *reinterpret_cast<uint32_t*>(&hv);
    lo = *reinterpret_cast<uint32_t*>(&lv);
}

// ---------------------------------------------------------------------------
// fp32 -> bf16 hi/lo split conversion (standalone)
// ---------------------------------------------------------------------------
__global__ __launch_bounds__(256)
void split_bf16(const float* __restrict__ in,
                __nv_bfloat16* __restrict__ hi,
                __nv_bfloat16* __restrict__ lo, int n4)
{
    int i = blockIdx.x * blockDim.x + threadIdx.x;
    if (i >= n4) return;
    int idx = i * 4;
    float4 v = *(const float4*)(in + idx);
    uint32_t h0, l0, h1, l1;
    split_pack(v.x, v.y, h0, l0);
    split_pack(v.z, v.w, h1, l1);
    *(uint2*)(hi + idx) = make_uint2(h0, h1);
    *(uint2*)(lo + idx) = make_uint2(l0, l1);
}

// ---------------------------------------------------------------------------
// HMMA (wmma) split-precision GEMM-NT with bias — 2-stage pipelined.
// C[m,n] = sum_k A[m,k]*B[n,k] + bias[n]  via  Ahi*Bhi + Alo*Bhi + Ahi*Blo.
// Block tile 128x128, K-chunk 16, 8 warps (4 M x 2 N), warp tile 32x64.
// ---------------------------------------------------------------------------
#define WBM 128
#define WBN 128
#define ASTR 24          // 16 + 8 pad (conflict-free, 16B-multiple)
#define BSTRIDE 132
static constexpr int GT = 128 * ASTR;                 // elems per operand tile
static constexpr int G_TILES_BYTES = 2 * 4 * GT * 2;  // 49152
static constexpr int G_SMEM = G_TILES_BYTES + 16 * BSTRIDE * 4;  // 57600

__global__ __launch_bounds__(256)
void gemm_wmma_split(const __nv_bfloat16* __restrict__ Ahi,
                     const __nv_bfloat16* __restrict__ Alo,
                     const __nv_bfloat16* __restrict__ Bhi,
                     const __nv_bfloat16* __restrict__ Blo,
                     const float* __restrict__ bias,
                     float* __restrict__ Cmat,
                     int M, int N, int K)
{
    extern __shared__ char gsm[];
    __nv_bfloat16* tiles = (__nv_bfloat16*)gsm;
    float* biasT = (float*)(gsm + G_TILES_BYTES);

    const int tid = threadIdx.x;
    const int wid = tid >> 5;
    const int wm = wid & 3;
    const int wn = wid >> 2;
    const int m0 = blockIdx.y * WBM;
    const int n0 = blockIdx.x * WBN;

    for (int i = tid; i < 16 * 128; i += 256) {
        int r = i >> 7, c = i & 127;
        biasT[r * BSTRIDE + c] = bias[n0 + c];
    }

    const int lr = tid >> 1;
    const int lc = (tid & 1) * 8;
    const __nv_bfloat16* srcs[4] = {
        Ahi + (size_t)(m0 + lr) * K + lc,
        Alo + (size_t)(m0 + lr) * K + lc,
        Bhi + (size_t)(n0 + lr) * K + lc,
        Blo + (size_t)(n0 + lr) * K + lc };

    // preload stage 0
    uint4 rg[4];
#pragma unroll
    for (int op = 0; op < 4; op++) rg[op] = *(const uint4*)(srcs[op]);
#pragma unroll
    for (int op = 0; op < 4; op++)
        *(uint4*)(tiles + op * GT + lr * ASTR + lc) = rg[op];
    __syncthreads();

    wmma::fragment<wmma::accumulator, 16, 16, 16, float> acc[2][4];
#pragma unroll
    for (int i = 0; i < 2; i++)
#pragma unroll
        for (int j = 0; j < 4; j++)
            wmma::load_matrix_sync(acc[i][j], &biasT[wn * 64 + j * 16],
                                   BSTRIDE, wmma::mem_row_major);

    int cur = 0;
    for (int k0 = 0; k0 < K; k0 += 16) {
        const bool more = (k0 + 16 < K);
        if (more) {
#pragma unroll
            for (int op = 0; op < 4; op++)
                rg[op] = *(const uint4*)(srcs[op] + k0 + 16);
        }

        __nv_bfloat16* sAh = tiles + (cur * 4 + 0) * GT;
        __nv_bfloat16* sAl = tiles + (cur * 4 + 1) * GT;
        __nv_bfloat16* sBh = tiles + (cur * 4 + 2) * GT;
        __nv_bfloat16* sBl = tiles + (cur * 4 + 3) * GT;

        wmma::fragment<wmma::matrix_a, 16, 16, 16, __nv_bfloat16, wmma::row_major> ah[2], al[2];
#pragma unroll
        for (int i = 0; i < 2; i++) {
            wmma::load_matrix_sync(ah[i], &sAh[(wm * 32 + i * 16) * ASTR], ASTR);
            wmma::load_matrix_sync(al[i], &sAl[(wm * 32 + i * 16) * ASTR], ASTR);
        }
#pragma unroll
        for (int j = 0; j < 4; j++) {
            wmma::fragment<wmma::matrix_b, 16, 16, 16, __nv_bfloat16, wmma::col_major> bh, bl;
            wmma::load_matrix_sync(bh, &sBh[(wn * 64 + j * 16) * ASTR], ASTR);
            wmma::load_matrix_sync(bl, &sBl[(wn * 64 + j * 16) * ASTR], ASTR);
#pragma unroll
            for (int i = 0; i < 2; i++) {
                wmma::mma_sync(acc[i][j], ah[i], bh, acc[i][j]);
                wmma::mma_sync(acc[i][j], al[i], bh, acc[i][j]);
                wmma::mma_sync(acc[i][j], ah[i], bl, acc[i][j]);
            }
        }
        if (more) {
            int nxt = cur ^ 1;
#pragma unroll
            for (int op = 0; op < 4; op++)
                *(uint4*)(tiles + (nxt * 4 + op) * GT + lr * ASTR + lc) = rg[op];
        }
        __syncthreads();
        cur ^= 1;
    }

#pragma unroll
    for (int i = 0; i < 2; i++)
#pragma unroll
        for (int j = 0; j < 4; j++)
            wmma::store_matrix_sync(
                &Cmat[(size_t)(m0 + wm * 32 + i * 16) * N + n0 + wn * 64 + j * 16],
                acc[i][j], N, wmma::mem_row_major);
}

// ---------------------------------------------------------------------------
// Flash attention, split-bf16 mma.sync.m16n8k16.
// Q tile 128 rows (8 warps x 16), K/V tiles 64. In-kernel fp32->hi/lo staging.
// P stays in registers (accumulator layout == next A layout).
// ---------------------------------------------------------------------------
static constexpr int AST = 72;   // smem row stride in bf16 elems (144B, conflict-free)
// smem elem offsets
static constexpr int O_QH = 0;
static constexpr int O_QL = O_QH + 128 * AST;
static constexpr int O_KH = O_QL + 128 * AST;
static constexpr int O_KL = O_KH + 64 * AST;
static constexpr int O_VH = O_KL + 64 * AST;
static constexpr int O_VL = O_VH + 64 * AST;
static constexpr int ATT_SMEM = (O_VL + 64 * AST) * 2;   // 73728 bytes

__global__ __launch_bounds__(256)
void attn_mma(const float* __restrict__ Q,
              const float* __restrict__ K,
              const float* __restrict__ V,
              float* __restrict__ Y)
{
    extern __shared__ char smraw[];
    __nv_bfloat16* sb = (__nv_bfloat16*)smraw;
    __nv_bfloat16* Qh = sb + O_QH;  __nv_bfloat16* Ql = sb + O_QL;
    __nv_bfloat16* Kh = sb + O_KH;  __nv_bfloat16* Kl = sb + O_KL;
    __nv_bfloat16* Vh = sb + O_VH;  __nv_bfloat16* Vl = sb + O_VL;

    const int qi = blockIdx.x, h = blockIdx.y, b = blockIdx.z;
    const int tid = threadIdx.x, wid = tid >> 5, lane = tid & 31;
    const int qb = qi * 128;
    const int wrow0 = wid * 16;
    const size_t gbase = (size_t)b * Tc * Cc + (size_t)h * Dc;

    // stage Q (128x64 fp32 -> hi/lo)
#pragma unroll
    for (int u = 0; u < 8; u++) {
        int id = tid + u * 256;
        int r = id >> 4, c = (id & 15) << 2;
        float4 v = *(const float4*)(Q + gbase + (size_t)(qb + r) * Cc + c);
        uint32_t h0, l0, h1, l1;
        split_pack(v.x, v.y, h0, l0);
        split_pack(v.z, v.w, h1, l1);
        *(uint2*)&Qh[r * AST + c] = make_uint2(h0, h1);
        *(uint2*)&Ql[r * AST + c] = make_uint2(l0, l1);
    }

    // ldsm address bases
    const uint32_t qh_u = smem_u32(Qh), ql_u = smem_u32(Ql);
    const uint32_t kh_u = smem_u32(Kh), kl_u = smem_u32(Kl);
    const uint32_t vh_u = smem_u32(Vh), vl_u = smem_u32(Vl);
    const int i7 = lane & 7, g = lane >> 3;
    const uint32_t aQoff = ((wrow0 + i7 + (g & 1) * 8) * AST + (g >> 1) * 8) * 2;
    const int l15 = lane & 15;
    const int bi = l15 & 7, bh8 = (l15 >> 3) * 8;

    float m_A = -1e30f, m_B = -1e30f, l_A = 0.f, l_B = 0.f;
    float oacc[8][4];
#pragma unroll
    for (int n = 0; n < 8; n++)
#pragma unroll
        for (int e = 0; e < 4; e++) oacc[n][e] = 0.f;

    const int nst = 2 * qi + 2;
    for (int st = 0; st < nst; st++) {
        __syncthreads();
        // stage K,V tile (64x64 fp32 -> hi/lo)
#pragma unroll
        for (int u = 0; u < 4; u++) {
            int id = tid + u * 256;
            int r = id >> 4, c = (id & 15) << 2;
            const size_t goff = gbase + (size_t)(st * 64 + r) * Cc + c;
            float4 kv = *(const float4*)(K + goff);
            uint32_t h0, l0, h1, l1;
            split_pack(kv.x, kv.y, h0, l0);
            split_pack(kv.z, kv.w, h1, l1);
            *(uint2*)&Kh[r * AST + c] = make_uint2(h0, h1);
            *(uint2*)&Kl[r * AST + c] = make_uint2(l0, l1);
            float4 vv = *(const float4*)(V + goff);
            split_pack(vv.x, vv.y, h0, l0);
            split_pack(vv.z, vv.w, h1, l1);
            *(uint2*)&Vh[r * AST + c] = make_uint2(h0, h1);
            *(uint2*)&Vl[r * AST + c] = make_uint2(l0, l1);
        }
        __syncthreads();

        // S = Q K^T  (3-term split)
        float sacc[8][4];
#pragma unroll
        for (int n = 0; n < 8; n++)
#pragma unroll
            for (int e = 0; e < 4; e++) sacc[n][e] = 0.f;

#pragma unroll
        for (int kk = 0; kk < 4; kk++) {
            uint32_t a0, a1, a2, a3, c0, c1, c2, c3;
            ldsm4(a0, a1, a2, a3, qh_u + aQoff + kk * 32);
            ldsm4(c0, c1, c2, c3, ql_u + aQoff + kk * 32);
#pragma unroll
            for (int n = 0; n < 8; n++) {
                const uint32_t boff = ((n * 8 + bi) * AST + bh8 + kk * 16) * 2;
                uint32_t bh0, bh1, bl0, bl1;
                ldsm2(bh0, bh1, kh_u + boff);
                ldsm2(bl0, bl1, kl_u + boff);
                mma16816(sacc[n], a0, a1, a2, a3, bh0, bh1);
                mma16816(sacc[n], c0, c1, c2, c3, bh0, bh1);
                mma16816(sacc[n], a0, a1, a2, a3, bl0, bl1);
            }
        }

        // scale + causal mask
#pragma unroll
        for (int n = 0; n < 8; n++)
#pragma unroll
            for (int e = 0; e < 4; e++) sacc[n][e] *= 0.125f;

        const int rA = lane >> 2;
        if (st >= 2 * qi) {
            const int rowAg = qb + wrow0 + rA;
            const int rowBg = rowAg + 8;
#pragma unroll
            for (int n = 0; n < 8; n++) {
                const int cg = st * 64 + n * 8 + (lane & 3) * 2;
                if (cg     > rowAg) sacc[n][0] = -1e30f;
                if (cg + 1 > rowAg) sacc[n][1] = -1e30f;
                if (cg     > rowBg) sacc[n][2] = -1e30f;
                if (cg + 1 > rowBg) sacc[n][3] = -1e30f;
            }
        }

        // online softmax
        float mA = -1e30f, mB = -1e30f;
#pragma unroll
        for (int n = 0; n < 8; n++) {
            mA = fmaxf(mA, fmaxf(sacc[n][0], sacc[n][1]));
            mB = fmaxf(mB, fmaxf(sacc[n][2], sacc[n][3]));
        }
        mA = fmaxf(mA, __shfl_xor_sync(0xffffffffu, mA, 1));
        mA = fmaxf(mA, __shfl_xor_sync(0xffffffffu, mA, 2));
        mB = fmaxf(mB, __shfl_xor_sync(0xffffffffu, mB, 1));
        mB = fmaxf(mB, __shfl_xor_sync(0xffffffffu, mB, 2));
        const float mnA = fmaxf(m_A, mA), mnB = fmaxf(m_B, mB);
        const float alA = __expf(m_A - mnA), alB = __expf(m_B - mnB);
        m_A = mnA; m_B = mnB;

        float lsA = 0.f, lsB = 0.f;
#pragma unroll
        for (int n = 0; n < 8; n++) {
            sacc[n][0] = __expf(sacc[n][0] - mnA);
            sacc[n][1] = __expf(sacc[n][1] - mnA);
            sacc[n][2] = __expf(sacc[n][2] - mnB);
            sacc[n][3] = __expf(sacc[n][3] - mnB);
            lsA += sacc[n][0] + sacc[n][1];
            lsB += sacc[n][2] + sacc[n][3];
        }
        lsA += __shfl_xor_sync(0xffffffffu, lsA, 1);
        lsA += __shfl_xor_sync(0xffffffffu, lsA, 2);
        lsB += __shfl_xor_sync(0xffffffffu, lsB, 1);
        lsB += __shfl_xor_sync(0xffffffffu, lsB, 2);
        l_A = l_A * alA + lsA;
        l_B = l_B * alB + lsB;
#pragma unroll
        for (int n = 0; n < 8; n++) {
            oacc[n][0] *= alA; oacc[n][1] *= alA;
            oacc[n][2] *= alB; oacc[n][3] *= alB;
        }

        // O += P V  (3-term split, P from registers)
#pragma unroll
        for (int ks = 0; ks < 4; ks++) {
            uint32_t ah0, ah1, ah2, ah3, al0, al1, al2, al3;
            split_pack(sacc[2 * ks][0],     sacc[2 * ks][1],     ah0, al0);
            split_pack(sacc[2 * ks][2],     sacc[2 * ks][3],     ah1, al1);
            split_pack(sacc[2 * ks + 1][0], sacc[2 * ks + 1][1], ah2, al2);
            split_pack(sacc[2 * ks + 1][2], sacc[2 * ks + 1][3], ah3, al3);
            const uint32_t vrow = (16 * ks + l15) * AST;
#pragma unroll
            for (int n = 0; n < 8; n++) {
                uint32_t bh0, bh1, bl0, bl1;
                ldsm2t(bh0, bh1, vh_u + (vrow + n * 8) * 2);
                ldsm2t(bl0, bl1, vl_u + (vrow + n * 8) * 2);
                mma16816(oacc[n], ah0, ah1, ah2, ah3, bh0, bh1);
                mma16816(oacc[n], al0, al1, al2, al3, bh0, bh1);
                mma16816(oacc[n], ah0, ah1, ah2, ah3, bl0, bl1);
            }
        }
    }

    // epilogue
    const float invA = 1.f / l_A, invB = 1.f / l_B;
    const int rowA = qb + wrow0 + (lane >> 2);
    const size_t ybA = ((size_t)b * Tc + rowA) * Cc + h * Dc + (lane & 3) * 2;
    const size_t ybB = ybA + (size_t)8 * Cc;
#pragma unroll
    for (int n = 0; n < 8; n++) {
        *(float2*)&Y[ybA + n * 8] = make_float2(oacc[n][0] * invA, oacc[n][1] * invA);
        *(float2*)&Y[ybB + n * 8] = make_float2(oacc[n][2] * invB, oacc[n][3] * invB);
    }
}

// ---------------------------------------------------------------------------
extern "C" void kernel_launch(void* const* d_in, const int* in_sizes, int n_in,
                              void* d_out, int out_size)
{
    (void)in_sizes; (void)n_in; (void)out_size;
    const float* x  = (const float*)d_in[0];
    const float* Wq = (const float*)d_in[1];
    const float* bq = (const float*)d_in[2];
    const float* Wk = (const float*)d_in[3];
    const float* bk = (const float*)d_in[4];
    const float* Wv = (const float*)d_in[5];
    const float* bv = (const float*)d_in[6];
    const float* Wp = (const float*)d_in[7];
    const float* bp = (const float*)d_in[8];
    float* out = (float*)d_out;

    float *q, *k, *v, *y;
    __nv_bfloat16 *xhi, *xlo, *yhi, *ylo, *whi, *wlo;
    cudaGetSymbolAddress((void**)&q, g_q);
    cudaGetSymbolAddress((void**)&k, g_k);
    cudaGetSymbolAddress((void**)&v, g_v);
    cudaGetSymbolAddress((void**)&y, g_y);
    cudaGetSymbolAddress((void**)&xhi, g_xhi);
    cudaGetSymbolAddress((void**)&xlo, g_xlo);
    cudaGetSymbolAddress((void**)&yhi, g_yhi);
    cudaGetSymbolAddress((void**)&ylo, g_ylo);
    cudaGetSymbolAddress((void**)&whi, g_whi);
    cudaGetSymbolAddress((void**)&wlo, g_wlo);

    cudaFuncSetAttribute(gemm_wmma_split,
                         cudaFuncAttributeMaxDynamicSharedMemorySize, G_SMEM);
    cudaFuncSetAttribute(attn_mma,
                         cudaFuncAttributeMaxDynamicSharedMemorySize, ATT_SMEM);

    // hi/lo splits
    split_bf16<<<(ELEMS / 4 + 255) / 256, 256>>>(x, xhi, xlo, ELEMS / 4);
    const float* Ws[4] = {Wq, Wk, Wv, Wp};
    for (int i = 0; i < 4; i++)
        split_bf16<<<(WELEMS / 4 + 255) / 256, 256>>>(
            Ws[i], whi + (size_t)i * WELEMS, wlo + (size_t)i * WELEMS, WELEMS / 4);

    // QKV projections (HMMA split precision, pipelined)
    dim3 gg(Cc / WBN, Mrows / WBM);   // (8, 64)
    gemm_wmma_split<<<gg, 256, G_SMEM>>>(xhi, xlo, whi + 0 * (size_t)WELEMS,
                                         wlo + 0 * (size_t)WELEMS, bq, q, Mrows, Cc, Cc);
    gemm_wmma_split<<<gg, 256, G_SMEM>>>(xhi, xlo, whi + 1 * (size_t)WELEMS,
                                         wlo + 1 * (size_t)WELEMS, bk, k, Mrows, Cc, Cc);
    gemm_wmma_split<<<gg, 256, G_SMEM>>>(xhi, xlo, whi + 2 * (size_t)WELEMS,
                                         wlo + 2 * (size_t)WELEMS, bv, v, Mrows, Cc, Cc);

    // attention (tensor-core split precision)
    dim3 ga(Tc / 128, Hc, Bc);        // (16, 16, 4)
    attn_mma<<<ga, 256, ATT_SMEM>>>(q, k, v, y);

    // output projection
    split_bf16<<<(ELEMS / 4 + 255) / 256, 256>>>(y, yhi, ylo, ELEMS / 4);
    gemm_wmma_split<<<gg, 256, G_SMEM>>>(yhi, ylo, whi + 3 * (size_t)WELEMS,
                                         wlo + 3 * (size_t)WELEMS, bp, out, Mrows, Cc, Cc);
}